// round 17
// baseline (speedup 1.0000x reference)
#include <cuda_runtime.h>
#include <cuda_fp16.h>

// Operator3D: bs=4, v=8192, n=20, SUPPORT=4, KERNEL=32  (S*K = 128)
// inputs: [0] neighbor_index int32 (bs,v,n)
//         [1] vertices       f32   (bs,v,3)
//         [2] weights        f32   (1,1,4,32)
//         [3] displacement   f32   (3,128)
// output: feature f32 (bs,v,32)
//
// R16 body (fp16 half2, 4-row fusion -- best measured) with refined launch
// geometry: 128-thread blocks (WPB=4), 2048 blocks, launch_bounds(128,11)
// -> 11 blocks/SM = 44 warps = ~69% occupancy (was 49% with 1.38 ragged
// waves of 256-thread blocks). Finer blocks also pack the tail wave evenly.
// Body unchanged: per j, 4 LDS.128 + 24 HFMA2 + 8 HMAX2 over 16 chains.

#define BS_   4
#define V_    8192
#define N_    20
#define K_    32
#define SK_   128
#define ROWS_ (BS_ * V_)

#define GR_      4
#define GITEMS_  (GR_ * N_)            // 80
#define GROUPS_  (ROWS_ / GR_)         // 8192

#define WPB      4
#define THREADS_ (WPB * 32)            // 128
#define BLOCKS_  (GROUPS_ / WPB)       // 2048

typedef unsigned int u32;

__device__ __forceinline__ u32 packh2(float lo, float hi) {  // {low=lo, high=hi}
    u32 r;
    asm("cvt.rn.f16x2.f32 %0, %1, %2;" : "=r"(r) : "f"(hi), "f"(lo));
    return r;
}
__device__ __forceinline__ __half2 u2h(u32 v) {
    __half2 h;
    *reinterpret_cast<u32*>(&h) = v;
    return h;
}

__global__ __launch_bounds__(THREADS_, 11)
void op3d_kernel(const int*   __restrict__ nb,
                 const float* __restrict__ verts,
                 const float* __restrict__ weights,
                 const float* __restrict__ disp,
                 float*       __restrict__ out)
{
    // per item: {(dx,dx),(dy,dy),(dz,dz),pad} as half2 -> one LDS.128 per item
    __shared__ uint4 sd[WPB][GITEMS_];

    const int warp = threadIdx.x >> 5;
    const int lane = threadIdx.x & 31;
    const int g    = blockIdx.x * WPB + warp;      // this warp's group
    const int r0   = g * GR_;

    // indices first: 3 coalesced LDGs in flight immediately (80 items)
    const int gb = g * GITEMS_;
    const int i0 = nb[gb + lane];
    const int i1 = nb[gb + 32 + lane];
    const int i2 = (lane < GITEMS_ - 64) ? nb[gb + 64 + lane] : 0;

    // per-lane constants (independent loads fill the idx wait)
    const __half2 D0_01 = u2h(packh2(disp[0*SK_ +  0 + lane], disp[0*SK_ + 32 + lane]));
    const __half2 D0_23 = u2h(packh2(disp[0*SK_ + 64 + lane], disp[0*SK_ + 96 + lane]));
    const __half2 D1_01 = u2h(packh2(disp[1*SK_ +  0 + lane], disp[1*SK_ + 32 + lane]));
    const __half2 D1_23 = u2h(packh2(disp[1*SK_ + 64 + lane], disp[1*SK_ + 96 + lane]));
    const __half2 D2_01 = u2h(packh2(disp[2*SK_ +  0 + lane], disp[2*SK_ + 32 + lane]));
    const __half2 D2_23 = u2h(packh2(disp[2*SK_ + 64 + lane], disp[2*SK_ + 96 + lane]));
    const float w0 = weights[ 0 + lane];
    const float w1 = weights[32 + lane];
    const float w2 = weights[64 + lane];
    const float w3 = weights[96 + lane];

    // batched gather: item -> row = item/20; fp32 diff -> duplicated half2
    {
        const int vbase = (r0 >> 13) * (V_ * 3);   // groups never span batches
        #define GATHER_(ITEM, IDX) do {                                      \
            const int   _it  = (ITEM);                                       \
            const int   _row = (int)((unsigned)_it / 20u);                   \
            const float* _p  = verts + vbase + (IDX) * 3;                    \
            const float* _q  = verts + (r0 + _row) * 3;                      \
            float _dx = _p[0]-_q[0], _dy = _p[1]-_q[1], _dz = _p[2]-_q[2];   \
            sd[warp][_it] = make_uint4(packh2(_dx,_dx), packh2(_dy,_dy),     \
                                       packh2(_dz,_dz), 0u);                 \
        } while (0)
        GATHER_(lane,      i0);
        GATHER_(lane + 32, i1);
        if (lane < GITEMS_ - 64) GATHER_(lane + 64, i2);
        #undef GATHER_
    }
    __syncwarp();

    // fused 4-row fp16 compute: 8 half2 max chains (16 scalar channels),
    // per j: 4 LDS.128 + 24 HFMA2-class + 8 HMAX2. max seeded 0 == relu.
    const __half2 zero = __float2half2_rn(0.0f);
    __half2 A01 = zero, A23 = zero;     // row 0
    __half2 B01 = zero, B23 = zero;     // row 1
    __half2 C01 = zero, C23 = zero;     // row 2
    __half2 E01 = zero, E23 = zero;     // row 3
    {
        const uint4* s0 = &sd[warp][0];
        const uint4* s1 = &sd[warp][N_];
        const uint4* s2 = &sd[warp][2 * N_];
        const uint4* s3 = &sd[warp][3 * N_];
        #pragma unroll
        for (int j = 0; j < N_; j++) {
            const uint4 A = s0[j];
            const uint4 B = s1[j];
            const uint4 C = s2[j];
            const uint4 E = s3[j];
            const __half2 ax = u2h(A.x), ay = u2h(A.y), az = u2h(A.z);
            const __half2 bx = u2h(B.x), by = u2h(B.y), bz = u2h(B.z);
            const __half2 cx = u2h(C.x), cy = u2h(C.y), cz = u2h(C.z);
            const __half2 ex = u2h(E.x), ey = u2h(E.y), ez = u2h(E.z);

            __half2 ta01 = __hfma2(ax, D0_01, __hfma2(ay, D1_01, __hmul2(az, D2_01)));
            __half2 tb01 = __hfma2(bx, D0_01, __hfma2(by, D1_01, __hmul2(bz, D2_01)));
            __half2 tc01 = __hfma2(cx, D0_01, __hfma2(cy, D1_01, __hmul2(cz, D2_01)));
            __half2 te01 = __hfma2(ex, D0_01, __hfma2(ey, D1_01, __hmul2(ez, D2_01)));
            __half2 ta23 = __hfma2(ax, D0_23, __hfma2(ay, D1_23, __hmul2(az, D2_23)));
            __half2 tb23 = __hfma2(bx, D0_23, __hfma2(by, D1_23, __hmul2(bz, D2_23)));
            __half2 tc23 = __hfma2(cx, D0_23, __hfma2(cy, D1_23, __hmul2(cz, D2_23)));
            __half2 te23 = __hfma2(ex, D0_23, __hfma2(ey, D1_23, __hmul2(ez, D2_23)));

            A01 = __hmax2(A01, ta01);
            B01 = __hmax2(B01, tb01);
            C01 = __hmax2(C01, tc01);
            E01 = __hmax2(E01, te01);
            A23 = __hmax2(A23, ta23);
            B23 = __hmax2(B23, tb23);
            C23 = __hmax2(C23, tc23);
            E23 = __hmax2(E23, te23);
        }
    }

    // fp32 epilogue: unpack maxes, weight, sum supports, store 4 rows
    {
        float m0, m1, m2, m3;
        m0 = __low2float(A01); m1 = __high2float(A01);
        m2 = __low2float(A23); m3 = __high2float(A23);
        out[ r0      * K_ + lane] = fmaf(m0, w0, fmaf(m1, w1, fmaf(m2, w2, m3 * w3)));
        m0 = __low2float(B01); m1 = __high2float(B01);
        m2 = __low2float(B23); m3 = __high2float(B23);
        out[(r0 + 1) * K_ + lane] = fmaf(m0, w0, fmaf(m1, w1, fmaf(m2, w2, m3 * w3)));
        m0 = __low2float(C01); m1 = __high2float(C01);
        m2 = __low2float(C23); m3 = __high2float(C23);
        out[(r0 + 2) * K_ + lane] = fmaf(m0, w0, fmaf(m1, w1, fmaf(m2, w2, m3 * w3)));
        m0 = __low2float(E01); m1 = __high2float(E01);
        m2 = __low2float(E23); m3 = __high2float(E23);
        out[(r0 + 3) * K_ + lane] = fmaf(m0, w0, fmaf(m1, w1, fmaf(m2, w2, m3 * w3)));
    }
}

extern "C" void kernel_launch(void* const* d_in, const int* in_sizes, int n_in,
                              void* d_out, int out_size)
{
    const int*   nb      = (const int*)  d_in[0];
    const float* verts   = (const float*)d_in[1];
    const float* weights = (const float*)d_in[2];
    const float* disp    = (const float*)d_in[3];
    float*       out     = (float*)      d_out;

    op3d_kernel<<<BLOCKS_, THREADS_>>>(nb, verts, weights, disp, out);
}